// round 5
// baseline (speedup 1.0000x reference)
#include <cuda_runtime.h>
#include <mma.h>
#include <cstdint>

using namespace nvcuda;

#define BATCH 8
#define SEQ   4096
#define DIM   512
#define DFF   2048
#define ROWS  (BATCH*SEQ)   /* 32768 */
#define HEADS 8
#define HD    64

// ---------------- scratch (device globals; no allocation allowed) ----------
__device__ float g_trend[(size_t)ROWS*DIM];
__device__ float g_seasonal[(size_t)ROWS*DIM];
__device__ float g_ln[(size_t)ROWS*DIM];
__device__ float g_q[(size_t)ROWS*DIM];
__device__ float g_k[(size_t)ROWS*DIM];
__device__ float g_v[(size_t)ROWS*DIM];
__device__ float g_attn[(size_t)ROWS*DIM];
__device__ float g_seasonal2[(size_t)ROWS*DIM];
__device__ float g_ffn1[(size_t)ROWS*DFF];
__device__ float g_kvp[(size_t)8*64*64*64];  // [chunk][bh][d][e]

// ---------------- helpers --------------------------------------------------
__device__ __forceinline__ float elu1f(float x) {
    return x > 0.f ? x + 1.f : expf(x);
}
__device__ __forceinline__ float geluf(float x) {
    return 0.5f * x * (1.f + erff(x * 0.7071067811865476f));
}

__device__ __forceinline__ void block_reduce2_128(float& s, float& q) {
    #pragma unroll
    for (int o = 16; o > 0; o >>= 1) {
        s += __shfl_xor_sync(0xffffffffu, s, o);
        q += __shfl_xor_sync(0xffffffffu, q, o);
    }
    __shared__ float rs[4], rq[4];
    int w = threadIdx.x >> 5, l = threadIdx.x & 31;
    if (l == 0) { rs[w] = s; rq[w] = q; }
    __syncthreads();
    s = rs[0] + rs[1] + rs[2] + rs[3];
    q = rq[0] + rq[1] + rq[2] + rq[3];
}

// ---------------- K1: series decomposition + LN1 ---------------------------
__global__ void decomp_ln_kernel(const float* __restrict__ x,
                                 const float* __restrict__ g1,
                                 const float* __restrict__ b1)
{
    size_t row = blockIdx.x;
    int n = (int)(row & (SEQ - 1));
    int tid = threadIdx.x;  // 128 threads, 4 floats each
    const float4* xr = (const float4*)(x + row * DIM);
    float4 xc = xr[tid];
    float4 xm = make_float4(0.f, 0.f, 0.f, 0.f);
    float4 xp = make_float4(0.f, 0.f, 0.f, 0.f);
    if (n > 0)       xm = xr[tid - 128];
    if (n < SEQ - 1) xp = xr[tid + 128];
    const float inv3 = 1.f / 3.f;
    float4 t, s;
    t.x = (xm.x + xc.x + xp.x) * inv3;  t.y = (xm.y + xc.y + xp.y) * inv3;
    t.z = (xm.z + xc.z + xp.z) * inv3;  t.w = (xm.w + xc.w + xp.w) * inv3;
    s.x = xc.x - t.x; s.y = xc.y - t.y; s.z = xc.z - t.z; s.w = xc.w - t.w;
    ((float4*)(g_trend    + row * DIM))[tid] = t;
    ((float4*)(g_seasonal + row * DIM))[tid] = s;

    float sum = s.x + s.y + s.z + s.w;
    float sq  = s.x*s.x + s.y*s.y + s.z*s.z + s.w*s.w;
    block_reduce2_128(sum, sq);
    float mean = sum * (1.f / DIM);
    float var  = sq * (1.f / DIM) - mean * mean;
    float rstd = rsqrtf(var + 1e-5f);
    float4 gg = ((const float4*)g1)[tid];
    float4 bb = ((const float4*)b1)[tid];
    float4 o;
    o.x = (s.x - mean) * rstd * gg.x + bb.x;
    o.y = (s.y - mean) * rstd * gg.y + bb.y;
    o.z = (s.z - mean) * rstd * gg.z + bb.z;
    o.w = (s.w - mean) * rstd * gg.w + bb.w;
    ((float4*)(g_ln + row * DIM))[tid] = o;
}

// ---------------- standalone LN --------------------------------------------
__global__ void ln_kernel(const float* __restrict__ in,
                          const float* __restrict__ g,
                          const float* __restrict__ b,
                          float* __restrict__ out)
{
    size_t row = blockIdx.x;
    int tid = threadIdx.x;
    float4 v = ((const float4*)(in + row * DIM))[tid];
    float sum = v.x + v.y + v.z + v.w;
    float sq  = v.x*v.x + v.y*v.y + v.z*v.z + v.w*v.w;
    block_reduce2_128(sum, sq);
    float mean = sum * (1.f / DIM);
    float var  = sq * (1.f / DIM) - mean * mean;
    float rstd = rsqrtf(var + 1e-5f);
    float4 gg = ((const float4*)g)[tid];
    float4 bb = ((const float4*)b)[tid];
    float4 o;
    o.x = (v.x - mean) * rstd * gg.x + bb.x;
    o.y = (v.y - mean) * rstd * gg.y + bb.y;
    o.z = (v.z - mean) * rstd * gg.z + bb.z;
    o.w = (v.w - mean) * rstd * gg.w + bb.w;
    ((float4*)(out + row * DIM))[tid] = o;
}

// ---------------- tf32x3 WMMA GEMM with fused epilogues ---------------------
// Error-compensated: a = hi + lo (each tf32), D = Ah*Bh + Ah*Bl + Al*Bh
// -> ~21 effective mantissa bits, fp32-class accuracy.
// C[M,N] = A[M,K] @ B[K,N] + bias, then:
//   EPI 0: nothing  1: elu+1  2: gelu(exact)  3: +add1  4: +add1+add2
// BM=128 BN=128 BK=32, 256 threads (8 warps, 2x4), warp tile 64x32 (4x2 frags)
#define GEMM_SMEM_FLOATS (128*136)
#define GEMM_SMEM_BYTES  (GEMM_SMEM_FLOATS*4)

template<int EPI>
__global__ void gemm_tf32_kernel(const float* __restrict__ A,
                                 const float* __restrict__ B,
                                 const float* __restrict__ bias,
                                 const float* __restrict__ add1,
                                 const float* __restrict__ add2,
                                 float* __restrict__ C,
                                 int M, int N, int K)
{
    extern __shared__ float smem[];
    const int AST = 40, BST = 136, CST = 132;
    float* As = smem;
    float* Bs = smem + 128 * AST;

    int tid = threadIdx.x;
    int warp = tid >> 5;
    int wm = warp >> 2;   // 0..1
    int wn = warp & 3;    // 0..3

    wmma::fragment<wmma::accumulator, 16, 16, 8, float> acc[4][2];
    #pragma unroll
    for (int i = 0; i < 4; i++)
        #pragma unroll
        for (int j = 0; j < 2; j++)
            wmma::fill_fragment(acc[i][j], 0.f);

    const size_t aBase = (size_t)blockIdx.y * 128 * K;
    const int nBase = blockIdx.x * 128;

    for (int k0 = 0; k0 < K; k0 += 32) {
        #pragma unroll
        for (int i = 0; i < 4; i++) {                 // A: 128x32
            int idx = tid + i * 256;
            int r = idx >> 3, c = (idx & 7) << 2;
            *(float4*)(As + r * AST + c) =
                *(const float4*)(A + aBase + (size_t)r * K + k0 + c);
        }
        #pragma unroll
        for (int i = 0; i < 4; i++) {                 // B: 32x128
            int idx = tid + i * 256;
            int r = idx >> 5, c = (idx & 31) << 2;
            *(float4*)(Bs + r * BST + c) =
                *(const float4*)(B + (size_t)(k0 + r) * N + nBase + c);
        }
        __syncthreads();
        #pragma unroll
        for (int kk = 0; kk < 32; kk += 8) {
            wmma::fragment<wmma::matrix_a, 16, 16, 8, wmma::precision::tf32, wmma::row_major> ah[4], al[4];
            wmma::fragment<wmma::matrix_b, 16, 16, 8, wmma::precision::tf32, wmma::row_major> bh[2], bl[2];
            #pragma unroll
            for (int i = 0; i < 4; i++) {
                wmma::load_matrix_sync(ah[i], As + (wm * 64 + i * 16) * AST + kk, AST);
                #pragma unroll
                for (int t = 0; t < ah[i].num_elements; t++) {
                    float full = ah[i].x[t];
                    float hi = wmma::__float_to_tf32(full);
                    ah[i].x[t] = hi;
                    al[i].x[t] = wmma::__float_to_tf32(full - hi);
                }
            }
            #pragma unroll
            for (int j = 0; j < 2; j++) {
                wmma::load_matrix_sync(bh[j], Bs + kk * BST + wn * 32 + j * 16, BST);
                #pragma unroll
                for (int t = 0; t < bh[j].num_elements; t++) {
                    float full = bh[j].x[t];
                    float hi = wmma::__float_to_tf32(full);
                    bh[j].x[t] = hi;
                    bl[j].x[t] = wmma::__float_to_tf32(full - hi);
                }
            }
            #pragma unroll
            for (int i = 0; i < 4; i++)
                #pragma unroll
                for (int j = 0; j < 2; j++) {
                    wmma::mma_sync(acc[i][j], al[i], bh[j], acc[i][j]);
                    wmma::mma_sync(acc[i][j], ah[i], bl[j], acc[i][j]);
                    wmma::mma_sync(acc[i][j], ah[i], bh[j], acc[i][j]);
                }
        }
        __syncthreads();
    }

    // stage C tile to smem, then fused epilogue
    float* Cs = smem;
    #pragma unroll
    for (int i = 0; i < 4; i++)
        #pragma unroll
        for (int j = 0; j < 2; j++)
            wmma::store_matrix_sync(Cs + (wm * 64 + i * 16) * CST + wn * 32 + j * 16,
                                    acc[i][j], CST, wmma::mem_row_major);
    __syncthreads();

    #pragma unroll
    for (int i = 0; i < 16; i++) {
        int idx = tid + i * 256;
        int r = idx >> 5, c = (idx & 31) << 2;
        size_t gr = (size_t)blockIdx.y * 128 + r;
        int gc = nBase + c;
        float4 v = *(float4*)(Cs + r * CST + c);
        float4 bv = *(const float4*)(bias + gc);
        v.x += bv.x; v.y += bv.y; v.z += bv.z; v.w += bv.w;
        if (EPI == 1) {
            v.x = elu1f(v.x); v.y = elu1f(v.y); v.z = elu1f(v.z); v.w = elu1f(v.w);
        } else if (EPI == 2) {
            v.x = geluf(v.x); v.y = geluf(v.y); v.z = geluf(v.z); v.w = geluf(v.w);
        } else if (EPI == 3) {
            float4 a1 = *(const float4*)(add1 + gr * N + gc);
            v.x += a1.x; v.y += a1.y; v.z += a1.z; v.w += a1.w;
        } else if (EPI == 4) {
            float4 a1 = *(const float4*)(add1 + gr * N + gc);
            float4 a2 = *(const float4*)(add2 + gr * N + gc);
            v.x += a1.x + a2.x; v.y += a1.y + a2.y;
            v.z += a1.z + a2.z; v.w += a1.w + a2.w;
        }
        *(float4*)(C + gr * (size_t)N + gc) = v;
    }
}

// ---------------- kv = sum_n k(n)⊗v(n), split-K partials -------------------
__global__ void kv_partial_kernel()
{
    int bh = blockIdx.x, chunk = blockIdx.y;
    int b = bh >> 3, h = bh & 7;
    size_t rowBase = (size_t)b * SEQ + chunk * 512;
    int colBase = h * 64;
    __shared__ float ks[32][64];
    __shared__ float vs[32][64];
    int tid = threadIdx.x;
    int d0 = (tid >> 4) << 2, e0 = (tid & 15) << 2;
    float acc[4][4];
    #pragma unroll
    for (int a = 0; a < 4; a++)
        #pragma unroll
        for (int c = 0; c < 4; c++) acc[a][c] = 0.f;

    for (int c0 = 0; c0 < 512; c0 += 32) {
        #pragma unroll
        for (int i = 0; i < 2; i++) {
            int idx = tid + i * 256;
            int r = idx >> 4, c = (idx & 15) << 2;
            size_t g = (rowBase + c0 + r) * DIM + colBase + c;
            *(float4*)&ks[r][c] = *(const float4*)(g_k + g);
            *(float4*)&vs[r][c] = *(const float4*)(g_v + g);
        }
        __syncthreads();
        #pragma unroll 8
        for (int i = 0; i < 32; i++) {
            float4 kk = *(float4*)&ks[i][d0];
            float4 vv = *(float4*)&vs[i][e0];
            acc[0][0] += kk.x * vv.x; acc[0][1] += kk.x * vv.y;
            acc[0][2] += kk.x * vv.z; acc[0][3] += kk.x * vv.w;
            acc[1][0] += kk.y * vv.x; acc[1][1] += kk.y * vv.y;
            acc[1][2] += kk.y * vv.z; acc[1][3] += kk.y * vv.w;
            acc[2][0] += kk.z * vv.x; acc[2][1] += kk.z * vv.y;
            acc[2][2] += kk.z * vv.z; acc[2][3] += kk.z * vv.w;
            acc[3][0] += kk.w * vv.x; acc[3][1] += kk.w * vv.y;
            acc[3][2] += kk.w * vv.z; acc[3][3] += kk.w * vv.w;
        }
        __syncthreads();
    }
    float* dst = g_kvp + ((size_t)chunk * 64 + bh) * 4096;
    #pragma unroll
    for (int a = 0; a < 4; a++) {
        float4 w = make_float4(acc[a][0], acc[a][1], acc[a][2], acc[a][3]);
        *(float4*)(dst + (d0 + a) * 64 + e0) = w;
    }
}

// ---------------- out = q @ kv ---------------------------------------------
__global__ void attn_out_kernel()
{
    int bh = blockIdx.x, nt = blockIdx.y;
    int b = bh >> 3, h = bh & 7;
    __shared__ float kv[64][64];
    __shared__ float qs[128][64];
    int tid = threadIdx.x;

    #pragma unroll
    for (int i = 0; i < 16; i++) {
        int idx = tid + i * 256;   // 0..4095
        float s = 0.f;
        #pragma unroll
        for (int c = 0; c < 8; c++)
            s += g_kvp[((size_t)c * 64 + bh) * 4096 + idx];
        ((float*)kv)[idx] = s;
    }
    size_t rowBase = (size_t)b * SEQ + nt * 128;
    int colBase = h * 64;
    #pragma unroll
    for (int i = 0; i < 8; i++) {
        int idx = tid + i * 256;
        int r = idx >> 4, c = (idx & 15) << 2;
        *(float4*)&qs[r][c] = *(const float4*)(g_q + (rowBase + r) * DIM + colBase + c);
    }
    __syncthreads();

    int e0 = (tid & 15) << 2;
    int r0 = (tid >> 4) << 3;
    #pragma unroll
    for (int rr = 0; rr < 8; rr++) {
        int r = r0 + rr;
        float4 a = make_float4(0.f, 0.f, 0.f, 0.f);
        #pragma unroll
        for (int d = 0; d < 64; d++) {
            float qv = qs[r][d];
            float4 kvv = *(float4*)&kv[d][e0];
            a.x += qv * kvv.x; a.y += qv * kvv.y;
            a.z += qv * kvv.z; a.w += qv * kvv.w;
        }
        *(float4*)(g_attn + (rowBase + r) * DIM + colBase + e0) = a;
    }
}

// ---------------- launch ----------------------------------------------------
extern "C" void kernel_launch(void* const* d_in, const int* in_sizes, int n_in,
                              void* d_out, int out_size)
{
    const float* x   = (const float*)d_in[0];
    const float* Wq  = (const float*)d_in[1];
    const float* bq  = (const float*)d_in[2];
    const float* Wk  = (const float*)d_in[3];
    const float* bk  = (const float*)d_in[4];
    const float* Wv  = (const float*)d_in[5];
    const float* bv  = (const float*)d_in[6];
    const float* Wo  = (const float*)d_in[7];
    const float* bo  = (const float*)d_in[8];
    const float* g1  = (const float*)d_in[9];
    const float* b1  = (const float*)d_in[10];
    const float* g2  = (const float*)d_in[11];
    const float* b2  = (const float*)d_in[12];
    const float* Wf1 = (const float*)d_in[13];
    const float* bf1 = (const float*)d_in[14];
    const float* Wf2 = (const float*)d_in[15];
    const float* bf2 = (const float*)d_in[16];
    float* out = (float*)d_out;

    cudaFuncSetAttribute(gemm_tf32_kernel<0>, cudaFuncAttributeMaxDynamicSharedMemorySize, GEMM_SMEM_BYTES);
    cudaFuncSetAttribute(gemm_tf32_kernel<1>, cudaFuncAttributeMaxDynamicSharedMemorySize, GEMM_SMEM_BYTES);
    cudaFuncSetAttribute(gemm_tf32_kernel<2>, cudaFuncAttributeMaxDynamicSharedMemorySize, GEMM_SMEM_BYTES);
    cudaFuncSetAttribute(gemm_tf32_kernel<3>, cudaFuncAttributeMaxDynamicSharedMemorySize, GEMM_SMEM_BYTES);
    cudaFuncSetAttribute(gemm_tf32_kernel<4>, cudaFuncAttributeMaxDynamicSharedMemorySize, GEMM_SMEM_BYTES);

    float *p_trend, *p_seasonal, *p_ln, *p_q, *p_k, *p_v, *p_attn, *p_s2, *p_ffn1;
    cudaGetSymbolAddress((void**)&p_trend,    g_trend);
    cudaGetSymbolAddress((void**)&p_seasonal, g_seasonal);
    cudaGetSymbolAddress((void**)&p_ln,       g_ln);
    cudaGetSymbolAddress((void**)&p_q,        g_q);
    cudaGetSymbolAddress((void**)&p_k,        g_k);
    cudaGetSymbolAddress((void**)&p_v,        g_v);
    cudaGetSymbolAddress((void**)&p_attn,     g_attn);
    cudaGetSymbolAddress((void**)&p_s2,       g_seasonal2);
    cudaGetSymbolAddress((void**)&p_ffn1,     g_ffn1);

    // 1) decomposition + LN1
    decomp_ln_kernel<<<ROWS, 128>>>(x, g1, b1);

    // 2) QKV projections (elu+1 fused on q,k)
    dim3 gqkv(DIM / 128, ROWS / 128);
    gemm_tf32_kernel<1><<<gqkv, 256, GEMM_SMEM_BYTES>>>(p_ln, Wq, bq, nullptr, nullptr, p_q, ROWS, DIM, DIM);
    gemm_tf32_kernel<1><<<gqkv, 256, GEMM_SMEM_BYTES>>>(p_ln, Wk, bk, nullptr, nullptr, p_k, ROWS, DIM, DIM);
    gemm_tf32_kernel<0><<<gqkv, 256, GEMM_SMEM_BYTES>>>(p_ln, Wv, bv, nullptr, nullptr, p_v, ROWS, DIM, DIM);

    // 3) linear attention
    kv_partial_kernel<<<dim3(64, 8), 256>>>();
    attn_out_kernel<<<dim3(64, SEQ / 128), 256>>>();

    // 4) output projection + residual -> seasonal2
    gemm_tf32_kernel<3><<<gqkv, 256, GEMM_SMEM_BYTES>>>(p_attn, Wo, bo, p_seasonal, nullptr, p_s2, ROWS, DIM, DIM);

    // 5) LN2
    ln_kernel<<<ROWS, 128>>>(p_s2, g2, b2, p_ln);

    // 6) FFN
    gemm_tf32_kernel<2><<<dim3(DFF / 128, ROWS / 128), 256, GEMM_SMEM_BYTES>>>(p_ln, Wf1, bf1, nullptr, nullptr, p_ffn1, ROWS, DFF, DIM);
    gemm_tf32_kernel<4><<<dim3(DIM / 128, ROWS / 128), 256, GEMM_SMEM_BYTES>>>(p_ffn1, Wf2, bf2, p_s2, p_trend, out, ROWS, DIM, DFF);
}

// round 6
// speedup vs baseline: 3.1863x; 3.1863x over previous
#include <cuda_runtime.h>
#include <cuda_bf16.h>
#include <mma.h>
#include <cstdint>

using namespace nvcuda;

#define BATCH 8
#define SEQ   4096
#define DIM   512
#define DFF   2048
#define ROWS  (BATCH*SEQ)   /* 32768 */
#define HEADS 8
#define HD    64

// ---------------- scratch (device globals; no allocation allowed) ----------
__device__ float g_trend[(size_t)ROWS*DIM];
__device__ float g_seasonal[(size_t)ROWS*DIM];
__device__ float g_ln[(size_t)ROWS*DIM];
__device__ float g_q[(size_t)ROWS*DIM];
__device__ float g_k[(size_t)ROWS*DIM];
__device__ float g_v[(size_t)ROWS*DIM];
__device__ float g_attn[(size_t)ROWS*DIM];
__device__ float g_seasonal2[(size_t)ROWS*DIM];
__device__ float g_ffn1[(size_t)ROWS*DFF];
__device__ float g_kvp[(size_t)8*64*64*64];  // [chunk][bh][d][e]

// ---------------- helpers --------------------------------------------------
__device__ __forceinline__ float elu1f(float x) {
    return x > 0.f ? x + 1.f : expf(x);
}
__device__ __forceinline__ float geluf(float x) {
    return 0.5f * x * (1.f + erff(x * 0.7071067811865476f));
}

__device__ __forceinline__ void block_reduce2_128(float& s, float& q) {
    #pragma unroll
    for (int o = 16; o > 0; o >>= 1) {
        s += __shfl_xor_sync(0xffffffffu, s, o);
        q += __shfl_xor_sync(0xffffffffu, q, o);
    }
    __shared__ float rs[4], rq[4];
    int w = threadIdx.x >> 5, l = threadIdx.x & 31;
    if (l == 0) { rs[w] = s; rq[w] = q; }
    __syncthreads();
    s = rs[0] + rs[1] + rs[2] + rs[3];
    q = rq[0] + rq[1] + rq[2] + rq[3];
}

// split one float4 into bf16 hi/lo planes
__device__ __forceinline__ void split_store4(__nv_bfloat16* hi, __nv_bfloat16* lo, float4 v) {
    float a0 = v.x, a1 = v.y, a2 = v.z, a3 = v.w;
    __nv_bfloat16 h0 = __float2bfloat16(a0);
    __nv_bfloat16 h1 = __float2bfloat16(a1);
    __nv_bfloat16 h2 = __float2bfloat16(a2);
    __nv_bfloat16 h3 = __float2bfloat16(a3);
    hi[0] = h0; hi[1] = h1; hi[2] = h2; hi[3] = h3;
    lo[0] = __float2bfloat16(a0 - __bfloat162float(h0));
    lo[1] = __float2bfloat16(a1 - __bfloat162float(h1));
    lo[2] = __float2bfloat16(a2 - __bfloat162float(h2));
    lo[3] = __float2bfloat16(a3 - __bfloat162float(h3));
}

// ---------------- K1: series decomposition + LN1 ---------------------------
__global__ void decomp_ln_kernel(const float* __restrict__ x,
                                 const float* __restrict__ g1,
                                 const float* __restrict__ b1)
{
    size_t row = blockIdx.x;
    int n = (int)(row & (SEQ - 1));
    int tid = threadIdx.x;  // 128 threads, 4 floats each
    const float4* xr = (const float4*)(x + row * DIM);
    float4 xc = xr[tid];
    float4 xm = make_float4(0.f, 0.f, 0.f, 0.f);
    float4 xp = make_float4(0.f, 0.f, 0.f, 0.f);
    if (n > 0)       xm = xr[tid - 128];
    if (n < SEQ - 1) xp = xr[tid + 128];
    const float inv3 = 1.f / 3.f;
    float4 t, s;
    t.x = (xm.x + xc.x + xp.x) * inv3;  t.y = (xm.y + xc.y + xp.y) * inv3;
    t.z = (xm.z + xc.z + xp.z) * inv3;  t.w = (xm.w + xc.w + xp.w) * inv3;
    s.x = xc.x - t.x; s.y = xc.y - t.y; s.z = xc.z - t.z; s.w = xc.w - t.w;
    ((float4*)(g_trend    + row * DIM))[tid] = t;
    ((float4*)(g_seasonal + row * DIM))[tid] = s;

    float sum = s.x + s.y + s.z + s.w;
    float sq  = s.x*s.x + s.y*s.y + s.z*s.z + s.w*s.w;
    block_reduce2_128(sum, sq);
    float mean = sum * (1.f / DIM);
    float var  = sq * (1.f / DIM) - mean * mean;
    float rstd = rsqrtf(var + 1e-5f);
    float4 gg = ((const float4*)g1)[tid];
    float4 bb = ((const float4*)b1)[tid];
    float4 o;
    o.x = (s.x - mean) * rstd * gg.x + bb.x;
    o.y = (s.y - mean) * rstd * gg.y + bb.y;
    o.z = (s.z - mean) * rstd * gg.z + bb.z;
    o.w = (s.w - mean) * rstd * gg.w + bb.w;
    ((float4*)(g_ln + row * DIM))[tid] = o;
}

// ---------------- standalone LN --------------------------------------------
__global__ void ln_kernel(const float* __restrict__ in,
                          const float* __restrict__ g,
                          const float* __restrict__ b,
                          float* __restrict__ out)
{
    size_t row = blockIdx.x;
    int tid = threadIdx.x;
    float4 v = ((const float4*)(in + row * DIM))[tid];
    float sum = v.x + v.y + v.z + v.w;
    float sq  = v.x*v.x + v.y*v.y + v.z*v.z + v.w*v.w;
    block_reduce2_128(sum, sq);
    float mean = sum * (1.f / DIM);
    float var  = sq * (1.f / DIM) - mean * mean;
    float rstd = rsqrtf(var + 1e-5f);
    float4 gg = ((const float4*)g)[tid];
    float4 bb = ((const float4*)b)[tid];
    float4 o;
    o.x = (v.x - mean) * rstd * gg.x + bb.x;
    o.y = (v.y - mean) * rstd * gg.y + bb.y;
    o.z = (v.z - mean) * rstd * gg.z + bb.z;
    o.w = (v.w - mean) * rstd * gg.w + bb.w;
    ((float4*)(out + row * DIM))[tid] = o;
}

// ---------------- bf16x2 WMMA GEMM with fused epilogues ---------------------
// Error-compensated split: a = hi + lo (each bf16), D = Ah*Bh + Ah*Bl + Al*Bh
// (split done ONCE at smem staging; ~2^-18 input error -> fp32-class result)
// C[M,N] = A[M,K] @ B[K,N] + bias, then:
//   EPI 0: nothing  1: elu+1  2: gelu(exact)  3: +add1  4: +add1+add2
// BM=128 BN=128 BK=32, 256 threads (8 warps, 2x4), warp tile 64x32 (4x2 frags)
#define AST 40     /* bf16 elems per A row  */
#define BST 136    /* bf16 elems per B row  */
#define CST 132    /* fp32 elems per C row  */
#define GEMM_SMEM_BYTES (128*CST*4)   /* 67584; conv planes fit inside */

template<int EPI>
__global__ void __launch_bounds__(256, 2)
gemm_bf16x2_kernel(const float* __restrict__ A,
                   const float* __restrict__ B,
                   const float* __restrict__ bias,
                   const float* __restrict__ add1,
                   const float* __restrict__ add2,
                   float* __restrict__ C,
                   int M, int N, int K)
{
    extern __shared__ float smem[];
    __nv_bfloat16* As_hi = (__nv_bfloat16*)smem;                 // 128*AST
    __nv_bfloat16* As_lo = As_hi + 128 * AST;
    __nv_bfloat16* Bs_hi = As_lo + 128 * AST;                    // 32*BST
    __nv_bfloat16* Bs_lo = Bs_hi + 32 * BST;

    int tid = threadIdx.x;
    int warp = tid >> 5;
    int wm = warp >> 2;   // 0..1
    int wn = warp & 3;    // 0..3

    wmma::fragment<wmma::accumulator, 16, 16, 16, float> acc[4][2];
    #pragma unroll
    for (int i = 0; i < 4; i++)
        #pragma unroll
        for (int j = 0; j < 2; j++)
            wmma::fill_fragment(acc[i][j], 0.f);

    const size_t aBase = (size_t)blockIdx.y * 128 * K;
    const int nBase = blockIdx.x * 128;

    for (int k0 = 0; k0 < K; k0 += 32) {
        #pragma unroll
        for (int i = 0; i < 4; i++) {                 // A: 128x32
            int idx = tid + i * 256;
            int r = idx >> 3, c = (idx & 7) << 2;
            float4 v = *(const float4*)(A + aBase + (size_t)r * K + k0 + c);
            split_store4(As_hi + r * AST + c, As_lo + r * AST + c, v);
        }
        #pragma unroll
        for (int i = 0; i < 4; i++) {                 // B: 32x128
            int idx = tid + i * 256;
            int r = idx >> 5, c = (idx & 31) << 2;
            float4 v = *(const float4*)(B + (size_t)(k0 + r) * N + nBase + c);
            split_store4(Bs_hi + r * BST + c, Bs_lo + r * BST + c, v);
        }
        __syncthreads();
        #pragma unroll
        for (int kk = 0; kk < 32; kk += 16) {
            wmma::fragment<wmma::matrix_a, 16, 16, 16, __nv_bfloat16, wmma::row_major> ah[4], al[4];
            wmma::fragment<wmma::matrix_b, 16, 16, 16, __nv_bfloat16, wmma::row_major> bh[2], bl[2];
            #pragma unroll
            for (int i = 0; i < 4; i++) {
                wmma::load_matrix_sync(ah[i], As_hi + (wm * 64 + i * 16) * AST + kk, AST);
                wmma::load_matrix_sync(al[i], As_lo + (wm * 64 + i * 16) * AST + kk, AST);
            }
            #pragma unroll
            for (int j = 0; j < 2; j++) {
                wmma::load_matrix_sync(bh[j], Bs_hi + kk * BST + wn * 32 + j * 16, BST);
                wmma::load_matrix_sync(bl[j], Bs_lo + kk * BST + wn * 32 + j * 16, BST);
            }
            #pragma unroll
            for (int i = 0; i < 4; i++)
                #pragma unroll
                for (int j = 0; j < 2; j++) {
                    wmma::mma_sync(acc[i][j], al[i], bh[j], acc[i][j]);
                    wmma::mma_sync(acc[i][j], ah[i], bl[j], acc[i][j]);
                    wmma::mma_sync(acc[i][j], ah[i], bh[j], acc[i][j]);
                }
        }
        __syncthreads();
    }

    // stage C tile to smem, then fused epilogue
    float* Cs = smem;
    #pragma unroll
    for (int i = 0; i < 4; i++)
        #pragma unroll
        for (int j = 0; j < 2; j++)
            wmma::store_matrix_sync(Cs + (wm * 64 + i * 16) * CST + wn * 32 + j * 16,
                                    acc[i][j], CST, wmma::mem_row_major);
    __syncthreads();

    #pragma unroll
    for (int i = 0; i < 16; i++) {
        int idx = tid + i * 256;
        int r = idx >> 5, c = (idx & 31) << 2;
        size_t gr = (size_t)blockIdx.y * 128 + r;
        int gc = nBase + c;
        float4 v = *(float4*)(Cs + r * CST + c);
        float4 bv = *(const float4*)(bias + gc);
        v.x += bv.x; v.y += bv.y; v.z += bv.z; v.w += bv.w;
        if (EPI == 1) {
            v.x = elu1f(v.x); v.y = elu1f(v.y); v.z = elu1f(v.z); v.w = elu1f(v.w);
        } else if (EPI == 2) {
            v.x = geluf(v.x); v.y = geluf(v.y); v.z = geluf(v.z); v.w = geluf(v.w);
        } else if (EPI == 3) {
            float4 a1 = *(const float4*)(add1 + gr * N + gc);
            v.x += a1.x; v.y += a1.y; v.z += a1.z; v.w += a1.w;
        } else if (EPI == 4) {
            float4 a1 = *(const float4*)(add1 + gr * N + gc);
            float4 a2 = *(const float4*)(add2 + gr * N + gc);
            v.x += a1.x + a2.x; v.y += a1.y + a2.y;
            v.z += a1.z + a2.z; v.w += a1.w + a2.w;
        }
        *(float4*)(C + gr * (size_t)N + gc) = v;
    }
}

// ---------------- kv = sum_n k(n)⊗v(n), split-K partials -------------------
__global__ void kv_partial_kernel()
{
    int bh = blockIdx.x, chunk = blockIdx.y;
    int b = bh >> 3, h = bh & 7;
    size_t rowBase = (size_t)b * SEQ + chunk * 512;
    int colBase = h * 64;
    __shared__ float ks[32][64];
    __shared__ float vs[32][64];
    int tid = threadIdx.x;
    int d0 = (tid >> 4) << 2, e0 = (tid & 15) << 2;
    float acc[4][4];
    #pragma unroll
    for (int a = 0; a < 4; a++)
        #pragma unroll
        for (int c = 0; c < 4; c++) acc[a][c] = 0.f;

    for (int c0 = 0; c0 < 512; c0 += 32) {
        #pragma unroll
        for (int i = 0; i < 2; i++) {
            int idx = tid + i * 256;
            int r = idx >> 4, c = (idx & 15) << 2;
            size_t g = (rowBase + c0 + r) * DIM + colBase + c;
            *(float4*)&ks[r][c] = *(const float4*)(g_k + g);
            *(float4*)&vs[r][c] = *(const float4*)(g_v + g);
        }
        __syncthreads();
        #pragma unroll 8
        for (int i = 0; i < 32; i++) {
            float4 kk = *(float4*)&ks[i][d0];
            float4 vv = *(float4*)&vs[i][e0];
            acc[0][0] += kk.x * vv.x; acc[0][1] += kk.x * vv.y;
            acc[0][2] += kk.x * vv.z; acc[0][3] += kk.x * vv.w;
            acc[1][0] += kk.y * vv.x; acc[1][1] += kk.y * vv.y;
            acc[1][2] += kk.y * vv.z; acc[1][3] += kk.y * vv.w;
            acc[2][0] += kk.z * vv.x; acc[2][1] += kk.z * vv.y;
            acc[2][2] += kk.z * vv.z; acc[2][3] += kk.z * vv.w;
            acc[3][0] += kk.w * vv.x; acc[3][1] += kk.w * vv.y;
            acc[3][2] += kk.w * vv.z; acc[3][3] += kk.w * vv.w;
        }
        __syncthreads();
    }
    float* dst = g_kvp + ((size_t)chunk * 64 + bh) * 4096;
    #pragma unroll
    for (int a = 0; a < 4; a++) {
        float4 w = make_float4(acc[a][0], acc[a][1], acc[a][2], acc[a][3]);
        *(float4*)(dst + (d0 + a) * 64 + e0) = w;
    }
}

// ---------------- out = q @ kv ---------------------------------------------
__global__ void attn_out_kernel()
{
    int bh = blockIdx.x, nt = blockIdx.y;
    int b = bh >> 3, h = bh & 7;
    __shared__ float kv[64][64];
    __shared__ float qs[128][64];
    int tid = threadIdx.x;

    #pragma unroll
    for (int i = 0; i < 16; i++) {
        int idx = tid + i * 256;   // 0..4095
        float s = 0.f;
        #pragma unroll
        for (int c = 0; c < 8; c++)
            s += g_kvp[((size_t)c * 64 + bh) * 4096 + idx];
        ((float*)kv)[idx] = s;
    }
    size_t rowBase = (size_t)b * SEQ + nt * 128;
    int colBase = h * 64;
    #pragma unroll
    for (int i = 0; i < 8; i++) {
        int idx = tid + i * 256;
        int r = idx >> 4, c = (idx & 15) << 2;
        *(float4*)&qs[r][c] = *(const float4*)(g_q + (rowBase + r) * DIM + colBase + c);
    }
    __syncthreads();

    int e0 = (tid & 15) << 2;
    int r0 = (tid >> 4) << 3;
    #pragma unroll
    for (int rr = 0; rr < 8; rr++) {
        int r = r0 + rr;
        float4 a = make_float4(0.f, 0.f, 0.f, 0.f);
        #pragma unroll
        for (int d = 0; d < 64; d++) {
            float qv = qs[r][d];
            float4 kvv = *(float4*)&kv[d][e0];
            a.x += qv * kvv.x; a.y += qv * kvv.y;
            a.z += qv * kvv.z; a.w += qv * kvv.w;
        }
        *(float4*)(g_attn + (rowBase + r) * DIM + colBase + e0) = a;
    }
}

// ---------------- launch ----------------------------------------------------
extern "C" void kernel_launch(void* const* d_in, const int* in_sizes, int n_in,
                              void* d_out, int out_size)
{
    const float* x   = (const float*)d_in[0];
    const float* Wq  = (const float*)d_in[1];
    const float* bq  = (const float*)d_in[2];
    const float* Wk  = (const float*)d_in[3];
    const float* bk  = (const float*)d_in[4];
    const float* Wv  = (const float*)d_in[5];
    const float* bv  = (const float*)d_in[6];
    const float* Wo  = (const float*)d_in[7];
    const float* bo  = (const float*)d_in[8];
    const float* g1  = (const float*)d_in[9];
    const float* b1  = (const float*)d_in[10];
    const float* g2  = (const float*)d_in[11];
    const float* b2  = (const float*)d_in[12];
    const float* Wf1 = (const float*)d_in[13];
    const float* bf1 = (const float*)d_in[14];
    const float* Wf2 = (const float*)d_in[15];
    const float* bf2 = (const float*)d_in[16];
    float* out = (float*)d_out;

    cudaFuncSetAttribute(gemm_bf16x2_kernel<0>, cudaFuncAttributeMaxDynamicSharedMemorySize, GEMM_SMEM_BYTES);
    cudaFuncSetAttribute(gemm_bf16x2_kernel<1>, cudaFuncAttributeMaxDynamicSharedMemorySize, GEMM_SMEM_BYTES);
    cudaFuncSetAttribute(gemm_bf16x2_kernel<2>, cudaFuncAttributeMaxDynamicSharedMemorySize, GEMM_SMEM_BYTES);
    cudaFuncSetAttribute(gemm_bf16x2_kernel<3>, cudaFuncAttributeMaxDynamicSharedMemorySize, GEMM_SMEM_BYTES);
    cudaFuncSetAttribute(gemm_bf16x2_kernel<4>, cudaFuncAttributeMaxDynamicSharedMemorySize, GEMM_SMEM_BYTES);

    float *p_trend, *p_seasonal, *p_ln, *p_q, *p_k, *p_v, *p_attn, *p_s2, *p_ffn1;
    cudaGetSymbolAddress((void**)&p_trend,    g_trend);
    cudaGetSymbolAddress((void**)&p_seasonal, g_seasonal);
    cudaGetSymbolAddress((void**)&p_ln,       g_ln);
    cudaGetSymbolAddress((void**)&p_q,        g_q);
    cudaGetSymbolAddress((void**)&p_k,        g_k);
    cudaGetSymbolAddress((void**)&p_v,        g_v);
    cudaGetSymbolAddress((void**)&p_attn,     g_attn);
    cudaGetSymbolAddress((void**)&p_s2,       g_seasonal2);
    cudaGetSymbolAddress((void**)&p_ffn1,     g_ffn1);

    // 1) decomposition + LN1
    decomp_ln_kernel<<<ROWS, 128>>>(x, g1, b1);

    // 2) QKV projections (elu+1 fused on q,k)
    dim3 gqkv(DIM / 128, ROWS / 128);
    gemm_bf16x2_kernel<1><<<gqkv, 256, GEMM_SMEM_BYTES>>>(p_ln, Wq, bq, nullptr, nullptr, p_q, ROWS, DIM, DIM);
    gemm_bf16x2_kernel<1><<<gqkv, 256, GEMM_SMEM_BYTES>>>(p_ln, Wk, bk, nullptr, nullptr, p_k, ROWS, DIM, DIM);
    gemm_bf16x2_kernel<0><<<gqkv, 256, GEMM_SMEM_BYTES>>>(p_ln, Wv, bv, nullptr, nullptr, p_v, ROWS, DIM, DIM);

    // 3) linear attention
    kv_partial_kernel<<<dim3(64, 8), 256>>>();
    attn_out_kernel<<<dim3(64, SEQ / 128), 256>>>();

    // 4) output projection + residual -> seasonal2
    gemm_bf16x2_kernel<3><<<gqkv, 256, GEMM_SMEM_BYTES>>>(p_attn, Wo, bo, p_seasonal, nullptr, p_s2, ROWS, DIM, DIM);

    // 5) LN2
    ln_kernel<<<ROWS, 128>>>(p_s2, g2, b2, p_ln);

    // 6) FFN
    gemm_bf16x2_kernel<2><<<dim3(DFF / 128, ROWS / 128), 256, GEMM_SMEM_BYTES>>>(p_ln, Wf1, bf1, nullptr, nullptr, p_ffn1, ROWS, DFF, DIM);
    gemm_bf16x2_kernel<4><<<dim3(DIM / 128, ROWS / 128), 256, GEMM_SMEM_BYTES>>>(p_ffn1, Wf2, bf2, p_s2, p_trend, out, ROWS, DIM, DFF);
}

// round 7
// speedup vs baseline: 3.2111x; 1.0078x over previous
#include <cuda_runtime.h>
#include <cuda_bf16.h>
#include <mma.h>
#include <cstdint>

using namespace nvcuda;

#define BATCH 8
#define SEQ   4096
#define DIM   512
#define DFF   2048
#define ROWS  (BATCH*SEQ)   /* 32768 */
#define HEADS 8
#define HD    64

// ---------------- scratch (device globals; no allocation allowed) ----------
__device__ float g_trend[(size_t)ROWS*DIM];
__device__ float g_seasonal[(size_t)ROWS*DIM];
__device__ float g_q[(size_t)ROWS*DIM];
__device__ float g_k[(size_t)ROWS*DIM];
__device__ float g_v[(size_t)ROWS*DIM];
__device__ float g_s2[(size_t)ROWS*DIM];
__device__ float g_kvp[(size_t)8*64*64*64];  // [chunk][bh][d][e]

// bf16 hi/lo planes (GEMM operands)
__device__ __nv_bfloat16 g_ln_hi[(size_t)ROWS*DIM];
__device__ __nv_bfloat16 g_ln_lo[(size_t)ROWS*DIM];
__device__ __nv_bfloat16 g_at_hi[(size_t)ROWS*DIM];
__device__ __nv_bfloat16 g_at_lo[(size_t)ROWS*DIM];
__device__ __nv_bfloat16 g_f1_hi[(size_t)ROWS*DFF];
__device__ __nv_bfloat16 g_f1_lo[(size_t)ROWS*DFF];

// weight planes: Wq,Wk,Wv,Wo (512x512 each), Wf1 (512x2048), Wf2 (2048x512)
#define WQ_OFF  0
#define WK_OFF  262144
#define WV_OFF  524288
#define WO_OFF  786432
#define WF1_OFF 1048576
#define WF2_OFF 2097152
#define WTOT    3145728
__device__ __nv_bfloat16 g_w_hi[WTOT];
__device__ __nv_bfloat16 g_w_lo[WTOT];

// ---------------- helpers --------------------------------------------------
__device__ __forceinline__ float elu1f(float x) {
    return x > 0.f ? x + 1.f : expf(x);
}
__device__ __forceinline__ float geluf(float x) {
    return 0.5f * x * (1.f + erff(x * 0.7071067811865476f));
}

// split 4 contiguous floats to hi/lo bf16 planes (8B store per plane)
__device__ __forceinline__ void split4_to(__nv_bfloat16* hi, __nv_bfloat16* lo, float4 v) {
    unsigned short h0 = __bfloat16_as_ushort(__float2bfloat16(v.x));
    unsigned short h1 = __bfloat16_as_ushort(__float2bfloat16(v.y));
    unsigned short h2 = __bfloat16_as_ushort(__float2bfloat16(v.z));
    unsigned short h3 = __bfloat16_as_ushort(__float2bfloat16(v.w));
    unsigned short l0 = __bfloat16_as_ushort(__float2bfloat16(v.x - __bfloat162float(__ushort_as_bfloat16(h0))));
    unsigned short l1 = __bfloat16_as_ushort(__float2bfloat16(v.y - __bfloat162float(__ushort_as_bfloat16(h1))));
    unsigned short l2 = __bfloat16_as_ushort(__float2bfloat16(v.z - __bfloat162float(__ushort_as_bfloat16(h2))));
    unsigned short l3 = __bfloat16_as_ushort(__float2bfloat16(v.w - __bfloat162float(__ushort_as_bfloat16(h3))));
    uint2 uh, ul;
    uh.x = (unsigned)h0 | ((unsigned)h1 << 16);
    uh.y = (unsigned)h2 | ((unsigned)h3 << 16);
    ul.x = (unsigned)l0 | ((unsigned)l1 << 16);
    ul.y = (unsigned)l2 | ((unsigned)l3 << 16);
    *(uint2*)hi = uh;
    *(uint2*)lo = ul;
}

__device__ __forceinline__ void block_reduce2_128(float& s, float& q) {
    #pragma unroll
    for (int o = 16; o > 0; o >>= 1) {
        s += __shfl_xor_sync(0xffffffffu, s, o);
        q += __shfl_xor_sync(0xffffffffu, q, o);
    }
    __shared__ float rs[4], rq[4];
    int w = threadIdx.x >> 5, l = threadIdx.x & 31;
    if (l == 0) { rs[w] = s; rq[w] = q; }
    __syncthreads();
    s = rs[0] + rs[1] + rs[2] + rs[3];
    q = rq[0] + rq[1] + rq[2] + rq[3];
}

// ---------------- weight fp32 -> bf16 hi/lo split --------------------------
__global__ void split_kernel(const float* __restrict__ in,
                             __nv_bfloat16* __restrict__ hi,
                             __nv_bfloat16* __restrict__ lo, int n4)
{
    int i = blockIdx.x * blockDim.x + threadIdx.x;
    if (i < n4) {
        float4 v = ((const float4*)in)[i];
        split4_to(hi + (size_t)i * 4, lo + (size_t)i * 4, v);
    }
}

// ---------------- K1: series decomposition + LN1 (emits hi/lo planes) ------
__global__ void decomp_ln_kernel(const float* __restrict__ x,
                                 const float* __restrict__ g1,
                                 const float* __restrict__ b1)
{
    size_t row = blockIdx.x;
    int n = (int)(row & (SEQ - 1));
    int tid = threadIdx.x;  // 128 threads, 4 floats each
    const float4* xr = (const float4*)(x + row * DIM);
    float4 xc = xr[tid];
    float4 xm = make_float4(0.f, 0.f, 0.f, 0.f);
    float4 xp = make_float4(0.f, 0.f, 0.f, 0.f);
    if (n > 0)       xm = xr[tid - 128];
    if (n < SEQ - 1) xp = xr[tid + 128];
    const float inv3 = 1.f / 3.f;
    float4 t, s;
    t.x = (xm.x + xc.x + xp.x) * inv3;  t.y = (xm.y + xc.y + xp.y) * inv3;
    t.z = (xm.z + xc.z + xp.z) * inv3;  t.w = (xm.w + xc.w + xp.w) * inv3;
    s.x = xc.x - t.x; s.y = xc.y - t.y; s.z = xc.z - t.z; s.w = xc.w - t.w;
    ((float4*)(g_trend    + row * DIM))[tid] = t;
    ((float4*)(g_seasonal + row * DIM))[tid] = s;

    float sum = s.x + s.y + s.z + s.w;
    float sq  = s.x*s.x + s.y*s.y + s.z*s.z + s.w*s.w;
    block_reduce2_128(sum, sq);
    float mean = sum * (1.f / DIM);
    float var  = sq * (1.f / DIM) - mean * mean;
    float rstd = rsqrtf(var + 1e-5f);
    float4 gg = ((const float4*)g1)[tid];
    float4 bb = ((const float4*)b1)[tid];
    float4 o;
    o.x = (s.x - mean) * rstd * gg.x + bb.x;
    o.y = (s.y - mean) * rstd * gg.y + bb.y;
    o.z = (s.z - mean) * rstd * gg.z + bb.z;
    o.w = (s.w - mean) * rstd * gg.w + bb.w;
    size_t idx = row * DIM + (size_t)tid * 4;
    split4_to(g_ln_hi + idx, g_ln_lo + idx, o);
}

// ---------------- LN2 (emits hi/lo planes) ----------------------------------
__global__ void ln_kernel(const float* __restrict__ in,
                          const float* __restrict__ g,
                          const float* __restrict__ b)
{
    size_t row = blockIdx.x;
    int tid = threadIdx.x;
    float4 v = ((const float4*)(in + row * DIM))[tid];
    float sum = v.x + v.y + v.z + v.w;
    float sq  = v.x*v.x + v.y*v.y + v.z*v.z + v.w*v.w;
    block_reduce2_128(sum, sq);
    float mean = sum * (1.f / DIM);
    float var  = sq * (1.f / DIM) - mean * mean;
    float rstd = rsqrtf(var + 1e-5f);
    float4 gg = ((const float4*)g)[tid];
    float4 bb = ((const float4*)b)[tid];
    float4 o;
    o.x = (v.x - mean) * rstd * gg.x + bb.x;
    o.y = (v.y - mean) * rstd * gg.y + bb.y;
    o.z = (v.z - mean) * rstd * gg.z + bb.z;
    o.w = (v.w - mean) * rstd * gg.w + bb.w;
    size_t idx = row * DIM + (size_t)tid * 4;
    split4_to(g_ln_hi + idx, g_ln_lo + idx, o);
}

// ---------------- pipelined bf16x2 WMMA GEMM --------------------------------
// Inputs are pre-split bf16 hi/lo planes. D = Ah*Bh + Ah*Bl + Al*Bh.
// 2-stage cp.async ping-pong, BM=128 BN=128 BK=32, 256 thr (8 warps 2x4).
//   EPI 0: none  1: elu+1  2: gelu  3: +add1  4: +add1+add2
//   OSPLIT 1: write hi/lo bf16 planes instead of fp32 C.
#define AST 40     /* bf16 elems per A smem row (80B = 5*16, odd -> LDSM-clean) */
#define BST 136    /* bf16 elems per B smem row (272B = 17*16) */
#define CST 132
#define A_PLANE_B (128*AST*2)                  /* 10240 */
#define B_PLANE_B (32*BST*2)                   /* 8704  */
#define STAGE_B   (2*A_PLANE_B + 2*B_PLANE_B)  /* 37888 */
#define GEMM_SMEM_BYTES (2*STAGE_B)            /* 75776; C stage (67584) fits */

__device__ __forceinline__ void cp16(uint32_t d, const void* s) {
    asm volatile("cp.async.cg.shared.global [%0], [%1], 16;\n" :: "r"(d), "l"(s));
}

template<int EPI, int OSPLIT>
__global__ void __launch_bounds__(256, 2)
gemm_pipe_kernel(const __nv_bfloat16* __restrict__ Ahi, const __nv_bfloat16* __restrict__ Alo,
                 const __nv_bfloat16* __restrict__ Bhi, const __nv_bfloat16* __restrict__ Blo,
                 const float* __restrict__ bias,
                 const float* __restrict__ add1, const float* __restrict__ add2,
                 float* __restrict__ C,
                 __nv_bfloat16* __restrict__ Chi, __nv_bfloat16* __restrict__ Clo,
                 int M, int N, int K)
{
    extern __shared__ char smem[];
    uint32_t sbase = (uint32_t)__cvta_generic_to_shared(smem);
    int tid = threadIdx.x;
    int warp = tid >> 5;
    int wm = warp >> 2;   // 0..1
    int wn = warp & 3;    // 0..3
    const size_t mBase = (size_t)blockIdx.y * 128;
    const int nBase = blockIdx.x * 128;

    // per-thread copy coordinates (2 chunks per plane)
    int ja0 = tid,        ja1 = tid + 256;            // A chunks 0..511
    int ar0 = ja0 >> 2,   ac0 = (ja0 & 3) << 4;       // dst byte offsets
    int ar1 = ja1 >> 2,   ac1 = (ja1 & 3) << 4;
    int br0 = ja0 >> 4,   bc0 = (ja0 & 15) << 4;
    int br1 = ja1 >> 4,   bc1 = (ja1 & 15) << 4;

    wmma::fragment<wmma::accumulator, 16, 16, 16, float> acc[4][2];
    #pragma unroll
    for (int i = 0; i < 4; i++)
        #pragma unroll
        for (int j = 0; j < 2; j++)
            wmma::fill_fragment(acc[i][j], 0.f);

    const int nIter = K >> 5;

    // tile copy: k-chunk index kt, stage st
    auto copy_tile = [&](int kt, int st) {
        uint32_t sb = sbase + st * STAGE_B;
        int k0 = kt << 5;
        size_t sa0 = (mBase + ar0) * K + k0 + ((ac0) >> 1);  // bytes->elems: 16B=8 elems
        size_t sa1 = (mBase + ar1) * K + k0 + ((ac1) >> 1);
        cp16(sb + ar0 * 80 + ac0, Ahi + sa0);
        cp16(sb + ar1 * 80 + ac1, Ahi + sa1);
        cp16(sb + A_PLANE_B + ar0 * 80 + ac0, Alo + sa0);
        cp16(sb + A_PLANE_B + ar1 * 80 + ac1, Alo + sa1);
        size_t sb0 = (size_t)(k0 + br0) * N + nBase + (bc0 >> 1);
        size_t sb1 = (size_t)(k0 + br1) * N + nBase + (bc1 >> 1);
        cp16(sb + 2 * A_PLANE_B + br0 * 272 + bc0, Bhi + sb0);
        cp16(sb + 2 * A_PLANE_B + br1 * 272 + bc1, Bhi + sb1);
        cp16(sb + 2 * A_PLANE_B + B_PLANE_B + br0 * 272 + bc0, Blo + sb0);
        cp16(sb + 2 * A_PLANE_B + B_PLANE_B + br1 * 272 + bc1, Blo + sb1);
    };

    copy_tile(0, 0);
    asm volatile("cp.async.commit_group;\n" ::);

    int buf = 0;
    for (int it = 0; it < nIter; it++) {
        asm volatile("cp.async.wait_group 0;\n" ::);
        __syncthreads();
        if (it + 1 < nIter) {
            copy_tile(it + 1, buf ^ 1);
            asm volatile("cp.async.commit_group;\n" ::);
        }
        const __nv_bfloat16* As_hi = (const __nv_bfloat16*)(smem + buf * STAGE_B);
        const __nv_bfloat16* As_lo = As_hi + 128 * AST;
        const __nv_bfloat16* Bs_hi = As_lo + 128 * AST;
        const __nv_bfloat16* Bs_lo = Bs_hi + 32 * BST;
        #pragma unroll
        for (int kk = 0; kk < 32; kk += 16) {
            wmma::fragment<wmma::matrix_a, 16, 16, 16, __nv_bfloat16, wmma::row_major> ah[4], al[4];
            wmma::fragment<wmma::matrix_b, 16, 16, 16, __nv_bfloat16, wmma::row_major> bh[2], bl[2];
            #pragma unroll
            for (int i = 0; i < 4; i++) {
                wmma::load_matrix_sync(ah[i], As_hi + (wm * 64 + i * 16) * AST + kk, AST);
                wmma::load_matrix_sync(al[i], As_lo + (wm * 64 + i * 16) * AST + kk, AST);
            }
            #pragma unroll
            for (int j = 0; j < 2; j++) {
                wmma::load_matrix_sync(bh[j], Bs_hi + kk * BST + wn * 32 + j * 16, BST);
                wmma::load_matrix_sync(bl[j], Bs_lo + kk * BST + wn * 32 + j * 16, BST);
            }
            #pragma unroll
            for (int i = 0; i < 4; i++)
                #pragma unroll
                for (int j = 0; j < 2; j++) {
                    wmma::mma_sync(acc[i][j], al[i], bh[j], acc[i][j]);
                    wmma::mma_sync(acc[i][j], ah[i], bl[j], acc[i][j]);
                    wmma::mma_sync(acc[i][j], ah[i], bh[j], acc[i][j]);
                }
        }
        buf ^= 1;
    }
    __syncthreads();

    // stage C tile to smem, then fused epilogue
    float* Cs = (float*)smem;
    #pragma unroll
    for (int i = 0; i < 4; i++)
        #pragma unroll
        for (int j = 0; j < 2; j++)
            wmma::store_matrix_sync(Cs + (wm * 64 + i * 16) * CST + wn * 32 + j * 16,
                                    acc[i][j], CST, wmma::mem_row_major);
    __syncthreads();

    #pragma unroll
    for (int i = 0; i < 16; i++) {
        int idx = tid + i * 256;
        int r = idx >> 5, c = (idx & 31) << 2;
        size_t gr = mBase + r;
        int gc = nBase + c;
        float4 v = *(float4*)(Cs + r * CST + c);
        float4 bv = *(const float4*)(bias + gc);
        v.x += bv.x; v.y += bv.y; v.z += bv.z; v.w += bv.w;
        if (EPI == 1) {
            v.x = elu1f(v.x); v.y = elu1f(v.y); v.z = elu1f(v.z); v.w = elu1f(v.w);
        } else if (EPI == 2) {
            v.x = geluf(v.x); v.y = geluf(v.y); v.z = geluf(v.z); v.w = geluf(v.w);
        } else if (EPI == 3) {
            float4 a1 = *(const float4*)(add1 + gr * N + gc);
            v.x += a1.x; v.y += a1.y; v.z += a1.z; v.w += a1.w;
        } else if (EPI == 4) {
            float4 a1 = *(const float4*)(add1 + gr * N + gc);
            float4 a2 = *(const float4*)(add2 + gr * N + gc);
            v.x += a1.x + a2.x; v.y += a1.y + a2.y;
            v.z += a1.z + a2.z; v.w += a1.w + a2.w;
        }
        if (OSPLIT) {
            split4_to(Chi + gr * (size_t)N + gc, Clo + gr * (size_t)N + gc, v);
        } else {
            *(float4*)(C + gr * (size_t)N + gc) = v;
        }
    }
}

// ---------------- kv = sum_n k(n)⊗v(n), split-K partials -------------------
__global__ void kv_partial_kernel()
{
    int bh = blockIdx.x, chunk = blockIdx.y;
    int b = bh >> 3, h = bh & 7;
    size_t rowBase = (size_t)b * SEQ + chunk * 512;
    int colBase = h * 64;
    __shared__ float ks[32][64];
    __shared__ float vs[32][64];
    int tid = threadIdx.x;
    int d0 = (tid >> 4) << 2, e0 = (tid & 15) << 2;
    float acc[4][4];
    #pragma unroll
    for (int a = 0; a < 4; a++)
        #pragma unroll
        for (int c = 0; c < 4; c++) acc[a][c] = 0.f;

    for (int c0 = 0; c0 < 512; c0 += 32) {
        #pragma unroll
        for (int i = 0; i < 2; i++) {
            int idx = tid + i * 256;
            int r = idx >> 4, c = (idx & 15) << 2;
            size_t g = (rowBase + c0 + r) * DIM + colBase + c;
            *(float4*)&ks[r][c] = *(const float4*)(g_k + g);
            *(float4*)&vs[r][c] = *(const float4*)(g_v + g);
        }
        __syncthreads();
        #pragma unroll 8
        for (int i = 0; i < 32; i++) {
            float4 kk = *(float4*)&ks[i][d0];
            float4 vv = *(float4*)&vs[i][e0];
            acc[0][0] += kk.x * vv.x; acc[0][1] += kk.x * vv.y;
            acc[0][2] += kk.x * vv.z; acc[0][3] += kk.x * vv.w;
            acc[1][0] += kk.y * vv.x; acc[1][1] += kk.y * vv.y;
            acc[1][2] += kk.y * vv.z; acc[1][3] += kk.y * vv.w;
            acc[2][0] += kk.z * vv.x; acc[2][1] += kk.z * vv.y;
            acc[2][2] += kk.z * vv.z; acc[2][3] += kk.z * vv.w;
            acc[3][0] += kk.w * vv.x; acc[3][1] += kk.w * vv.y;
            acc[3][2] += kk.w * vv.z; acc[3][3] += kk.w * vv.w;
        }
        __syncthreads();
    }
    float* dst = g_kvp + ((size_t)chunk * 64 + bh) * 4096;
    #pragma unroll
    for (int a = 0; a < 4; a++) {
        float4 w = make_float4(acc[a][0], acc[a][1], acc[a][2], acc[a][3]);
        *(float4*)(dst + (d0 + a) * 64 + e0) = w;
    }
}

// ---------------- out = q @ kv (emits hi/lo planes) -------------------------
__global__ void attn_out_kernel()
{
    int bh = blockIdx.x, nt = blockIdx.y;
    int b = bh >> 3, h = bh & 7;
    __shared__ float kv[64][64];
    __shared__ float qs[128][64];
    int tid = threadIdx.x;

    #pragma unroll
    for (int i = 0; i < 16; i++) {
        int idx = tid + i * 256;   // 0..4095
        float s = 0.f;
        #pragma unroll
        for (int c = 0; c < 8; c++)
            s += g_kvp[((size_t)c * 64 + bh) * 4096 + idx];
        ((float*)kv)[idx] = s;
    }
    size_t rowBase = (size_t)b * SEQ + nt * 128;
    int colBase = h * 64;
    #pragma unroll
    for (int i = 0; i < 8; i++) {
        int idx = tid + i * 256;
        int r = idx >> 4, c = (idx & 15) << 2;
        *(float4*)&qs[r][c] = *(const float4*)(g_q + (rowBase + r) * DIM + colBase + c);
    }
    __syncthreads();

    int e0 = (tid & 15) << 2;
    int r0 = (tid >> 4) << 3;
    #pragma unroll
    for (int rr = 0; rr < 8; rr++) {
        int r = r0 + rr;
        float4 a = make_float4(0.f, 0.f, 0.f, 0.f);
        #pragma unroll
        for (int d = 0; d < 64; d++) {
            float qv = qs[r][d];
            float4 kvv = *(float4*)&kv[d][e0];
            a.x += qv * kvv.x; a.y += qv * kvv.y;
            a.z += qv * kvv.z; a.w += qv * kvv.w;
        }
        size_t idx = (rowBase + r) * DIM + colBase + e0;
        split4_to(g_at_hi + idx, g_at_lo + idx, a);
    }
}

// ---------------- launch ----------------------------------------------------
extern "C" void kernel_launch(void* const* d_in, const int* in_sizes, int n_in,
                              void* d_out, int out_size)
{
    const float* x   = (const float*)d_in[0];
    const float* Wq  = (const float*)d_in[1];
    const float* bq  = (const float*)d_in[2];
    const float* Wk  = (const float*)d_in[3];
    const float* bk  = (const float*)d_in[4];
    const float* Wv  = (const float*)d_in[5];
    const float* bv  = (const float*)d_in[6];
    const float* Wo  = (const float*)d_in[7];
    const float* bo  = (const float*)d_in[8];
    const float* g1  = (const float*)d_in[9];
    const float* b1  = (const float*)d_in[10];
    const float* g2  = (const float*)d_in[11];
    const float* b2  = (const float*)d_in[12];
    const float* Wf1 = (const float*)d_in[13];
    const float* bf1 = (const float*)d_in[14];
    const float* Wf2 = (const float*)d_in[15];
    const float* bf2 = (const float*)d_in[16];
    float* out = (float*)d_out;

    cudaFuncSetAttribute(gemm_pipe_kernel<0,0>, cudaFuncAttributeMaxDynamicSharedMemorySize, GEMM_SMEM_BYTES);
    cudaFuncSetAttribute(gemm_pipe_kernel<1,0>, cudaFuncAttributeMaxDynamicSharedMemorySize, GEMM_SMEM_BYTES);
    cudaFuncSetAttribute(gemm_pipe_kernel<2,1>, cudaFuncAttributeMaxDynamicSharedMemorySize, GEMM_SMEM_BYTES);
    cudaFuncSetAttribute(gemm_pipe_kernel<3,0>, cudaFuncAttributeMaxDynamicSharedMemorySize, GEMM_SMEM_BYTES);
    cudaFuncSetAttribute(gemm_pipe_kernel<4,0>, cudaFuncAttributeMaxDynamicSharedMemorySize, GEMM_SMEM_BYTES);

    float *p_trend, *p_seasonal, *p_q, *p_k, *p_v, *p_s2;
    __nv_bfloat16 *p_ln_hi, *p_ln_lo, *p_at_hi, *p_at_lo, *p_f1_hi, *p_f1_lo, *p_w_hi, *p_w_lo;
    cudaGetSymbolAddress((void**)&p_trend,    g_trend);
    cudaGetSymbolAddress((void**)&p_seasonal, g_seasonal);
    cudaGetSymbolAddress((void**)&p_q,        g_q);
    cudaGetSymbolAddress((void**)&p_k,        g_k);
    cudaGetSymbolAddress((void**)&p_v,        g_v);
    cudaGetSymbolAddress((void**)&p_s2,       g_s2);
    cudaGetSymbolAddress((void**)&p_ln_hi,    g_ln_hi);
    cudaGetSymbolAddress((void**)&p_ln_lo,    g_ln_lo);
    cudaGetSymbolAddress((void**)&p_at_hi,    g_at_hi);
    cudaGetSymbolAddress((void**)&p_at_lo,    g_at_lo);
    cudaGetSymbolAddress((void**)&p_f1_hi,    g_f1_hi);
    cudaGetSymbolAddress((void**)&p_f1_lo,    g_f1_lo);
    cudaGetSymbolAddress((void**)&p_w_hi,     g_w_hi);
    cudaGetSymbolAddress((void**)&p_w_lo,     g_w_lo);

    // 0) split weights into bf16 hi/lo planes (cheap; runs every replay)
    split_kernel<<<(262144/4 + 255)/256, 256>>>(Wq,  p_w_hi + WQ_OFF,  p_w_lo + WQ_OFF,  262144/4);
    split_kernel<<<(262144/4 + 255)/256, 256>>>(Wk,  p_w_hi + WK_OFF,  p_w_lo + WK_OFF,  262144/4);
    split_kernel<<<(262144/4 + 255)/256, 256>>>(Wv,  p_w_hi + WV_OFF,  p_w_lo + WV_OFF,  262144/4);
    split_kernel<<<(262144/4 + 255)/256, 256>>>(Wo,  p_w_hi + WO_OFF,  p_w_lo + WO_OFF,  262144/4);
    split_kernel<<<(1048576/4 + 255)/256, 256>>>(Wf1, p_w_hi + WF1_OFF, p_w_lo + WF1_OFF, 1048576/4);
    split_kernel<<<(1048576/4 + 255)/256, 256>>>(Wf2, p_w_hi + WF2_OFF, p_w_lo + WF2_OFF, 1048576/4);

    // 1) decomposition + LN1 -> ln planes
    decomp_ln_kernel<<<ROWS, 128>>>(x, g1, b1);

    // 2) QKV projections (elu+1 fused on q,k), fp32 outputs for attention
    dim3 gqkv(DIM / 128, ROWS / 128);
    gemm_pipe_kernel<1,0><<<gqkv, 256, GEMM_SMEM_BYTES>>>(p_ln_hi, p_ln_lo, p_w_hi + WQ_OFF, p_w_lo + WQ_OFF,
                                                          bq, nullptr, nullptr, p_q, nullptr, nullptr, ROWS, DIM, DIM);
    gemm_pipe_kernel<1,0><<<gqkv, 256, GEMM_SMEM_BYTES>>>(p_ln_hi, p_ln_lo, p_w_hi + WK_OFF, p_w_lo + WK_OFF,
                                                          bk, nullptr, nullptr, p_k, nullptr, nullptr, ROWS, DIM, DIM);
    gemm_pipe_kernel<0,0><<<gqkv, 256, GEMM_SMEM_BYTES>>>(p_ln_hi, p_ln_lo, p_w_hi + WV_OFF, p_w_lo + WV_OFF,
                                                          bv, nullptr, nullptr, p_v, nullptr, nullptr, ROWS, DIM, DIM);

    // 3) linear attention -> attn planes
    kv_partial_kernel<<<dim3(64, 8), 256>>>();
    attn_out_kernel<<<dim3(64, SEQ / 128), 256>>>();

    // 4) output projection + residual -> s2 (fp32)
    gemm_pipe_kernel<3,0><<<gqkv, 256, GEMM_SMEM_BYTES>>>(p_at_hi, p_at_lo, p_w_hi + WO_OFF, p_w_lo + WO_OFF,
                                                          bo, p_seasonal, nullptr, p_s2, nullptr, nullptr, ROWS, DIM, DIM);

    // 5) LN2 -> ln planes (reuse)
    ln_kernel<<<ROWS, 128>>>(p_s2, g2, b2);

    // 6) FFN: FFN1 emits gelu hi/lo planes; FFN2 fuses both residuals
    gemm_pipe_kernel<2,1><<<dim3(DFF / 128, ROWS / 128), 256, GEMM_SMEM_BYTES>>>(
        p_ln_hi, p_ln_lo, p_w_hi + WF1_OFF, p_w_lo + WF1_OFF,
        bf1, nullptr, nullptr, nullptr, p_f1_hi, p_f1_lo, ROWS, DFF, DIM);
    gemm_pipe_kernel<4,0><<<dim3(DIM / 128, ROWS / 128), 256, GEMM_SMEM_BYTES>>>(
        p_f1_hi, p_f1_lo, p_w_hi + WF2_OFF, p_w_lo + WF2_OFF,
        bf2, p_s2, p_trend, out, nullptr, nullptr, ROWS, DIM, DFF);
}